// round 1
// baseline (speedup 1.0000x reference)
#include <cuda_runtime.h>
#include <math.h>

#define BB 2048
#define TT 16
#define RR 2048
#define TPB 256
#define NPAIR 15

// Scratch: __device__ globals (no allocation allowed).
__device__ float    g_part[NPAIR * BB];   // [t][b] = S(b,t) * pair_valid(b,t)
__device__ float    g_bce[BB];            // per-b sum of bce*vm
__device__ float    g_vms[BB];            // per-b sum of vm
__device__ unsigned g_pv[BB];             // per-b packed pair_valid bits (15 bits)

__device__ __forceinline__ float log_sigmoid(float x) {
    // stable: min(x,0) - log1p(exp(-|x|))
    return fminf(x, 0.f) - log1pf(__expf(-fabsf(x)));
}

__device__ __forceinline__ float pen1(float a, float b) {
    float d = fabsf(a - b);
    float e = fmaxf(d - 0.2f, 0.f);
    return e * e;
}

__global__ __launch_bounds__(TPB)
void smooth_kernel(const float* __restrict__ pred,
                   const float* __restrict__ rs,
                   const int*   __restrict__ tgt,
                   const int*   __restrict__ vmask)
{
    const int b   = blockIdx.x;
    const int tid = threadIdx.x;

    __shared__ float s_vm[TT];
    __shared__ float s_bce[TT];
    __shared__ float red[NPAIR][TPB / 32];

    // ---- tiny BCE part: threads 0..15 handle the 16 timesteps of this b ----
    if (tid < TT) {
        int idx   = b * TT + tid;
        float v   = (float)vmask[idx];
        float y   = (float)tgt[idx];
        float p   = pred[idx];
        // pos_weight = 2.0
        float bce = -(2.f * y * log_sigmoid(p) + (1.f - y) * log_sigmoid(-p));
        s_vm[tid]  = v;
        s_bce[tid] = bce * v;
    }

    // ---- streaming smoothness: each thread owns 8 r columns (2 float4) ----
    const float4* base = (const float4*)rs + (size_t)b * TT * (RR / 4);
    float4 p0 = base[tid];
    float4 p1 = base[tid + TPB];

    float acc[NPAIR];
#pragma unroll
    for (int t = 0; t < NPAIR; t++) acc[t] = 0.f;

#pragma unroll
    for (int t = 1; t < TT; t++) {
        float4 c0 = base[t * (RR / 4) + tid];
        float4 c1 = base[t * (RR / 4) + tid + TPB];
        float a = 0.f;
        a += pen1(c0.x, p0.x);  a += pen1(c0.y, p0.y);
        a += pen1(c0.z, p0.z);  a += pen1(c0.w, p0.w);
        a += pen1(c1.x, p1.x);  a += pen1(c1.y, p1.y);
        a += pen1(c1.z, p1.z);  a += pen1(c1.w, p1.w);
        acc[t - 1] = a;
        p0 = c0; p1 = c1;
    }

    // ---- block reduction of the 15 per-t sums ----
    const int lane = tid & 31, wid = tid >> 5;
#pragma unroll
    for (int t = 0; t < NPAIR; t++) {
        float v = acc[t];
#pragma unroll
        for (int o = 16; o; o >>= 1) v += __shfl_xor_sync(0xffffffffu, v, o);
        if (lane == 0) red[t][wid] = v;
    }
    __syncthreads();

    if (tid < NPAIR) {
        float s = 0.f;
#pragma unroll
        for (int w = 0; w < TPB / 32; w++) s += red[tid][w];
        float pv = (s_vm[tid] > 0.5f && s_vm[tid + 1] > 0.5f) ? 1.f : 0.f;
        g_part[tid * BB + b] = s * pv;   // [t][b] layout for coalesced finalize
    }
    if (tid == 0) {
        float bs = 0.f, vs = 0.f;
        unsigned bits = 0;
#pragma unroll
        for (int t = 0; t < TT; t++) { bs += s_bce[t]; vs += s_vm[t]; }
#pragma unroll
        for (int t = 0; t < NPAIR; t++)
            if (s_vm[t] > 0.5f && s_vm[t + 1] > 0.5f) bits |= 1u << t;
        g_bce[b] = bs;
        g_vms[b] = vs;
        g_pv[b]  = bits;
    }
}

__global__ __launch_bounds__(256)
void finalize_kernel(float* __restrict__ out)
{
    const int tid = threadIdx.x;

    float sums[NPAIR], cnt[NPAIR];
#pragma unroll
    for (int t = 0; t < NPAIR; t++) { sums[t] = 0.f; cnt[t] = 0.f; }
    float bs = 0.f, vs = 0.f;

    for (int b = tid; b < BB; b += 256) {
        unsigned bits = g_pv[b];
        bs += g_bce[b];
        vs += g_vms[b];
#pragma unroll
        for (int t = 0; t < NPAIR; t++) {
            sums[t] += g_part[t * BB + b];
            cnt[t]  += (float)((bits >> t) & 1u);
        }
    }

    // reduce 32 scalars: warp shfl then shared atomics from lane 0
    __shared__ float sred[32];
    if (tid < 32) sred[tid] = 0.f;
    __syncthreads();

    const int lane = tid & 31;
    float vals[32];
#pragma unroll
    for (int t = 0; t < NPAIR; t++) { vals[t] = sums[t]; vals[NPAIR + t] = cnt[t]; }
    vals[30] = bs; vals[31] = vs;
#pragma unroll
    for (int k = 0; k < 32; k++) {
        float v = vals[k];
#pragma unroll
        for (int o = 16; o; o >>= 1) v += __shfl_xor_sync(0xffffffffu, v, o);
        if (lane == 0) atomicAdd(&sred[k], v);
    }
    __syncthreads();

    if (tid == 0) {
        float ssum = 0.f;
        int ns = 0;
#pragma unroll
        for (int t = 0; t < NPAIR; t++) {
            float c = sred[NPAIR + t];
            if (c > 0.f) ns++;
            ssum += sred[t] / ((float)RR * fmaxf(c, 1.f));
        }
        float smooth = (ns > 0) ? (ssum / (float)ns) : 0.f;
        float cls    = sred[30] / fmaxf(sred[31], 1e-8f);
        out[0] = cls + 0.2f * smooth;
    }
}

extern "C" void kernel_launch(void* const* d_in, const int* in_sizes, int n_in,
                              void* d_out, int out_size)
{
    const float* pred  = (const float*)d_in[0];  // [B,T,1]
    const float* rs    = (const float*)d_in[1];  // [B,T,R,1]
    const int*   tgt   = (const int*)d_in[2];    // [B,T]
    const int*   vmask = (const int*)d_in[3];    // [B,T]
    float*       out   = (float*)d_out;

    smooth_kernel<<<BB, TPB>>>(pred, rs, tgt, vmask);
    finalize_kernel<<<1, 256>>>(out);
}

// round 2
// speedup vs baseline: 1.2493x; 1.2493x over previous
#include <cuda_runtime.h>
#include <math.h>

#define BB 2048
#define TT 16
#define RR 2048
#define TPB 256
#define NPAIR 15

// 32 accumulator slots: [0..14] step sums, [15..29] step counts,
// [30] bce*vm sum, [31] vm sum. Zero at module load; finalize re-zeroes
// after each use so graph replays always start from zeros.
__device__ float g_acc[32];

__device__ __forceinline__ float log_sigmoid(float x) {
    // stable: min(x,0) - log1p(exp(-|x|))
    return fminf(x, 0.f) - log1pf(__expf(-fabsf(x)));
}

__device__ __forceinline__ float pen1(float a, float b) {
    float d = fabsf(a - b);
    float e = fmaxf(d - 0.2f, 0.f);
    return e * e;
}

__global__ __launch_bounds__(TPB)
void smooth_kernel(const float* __restrict__ pred,
                   const float* __restrict__ rs,
                   const int*   __restrict__ tgt,
                   const int*   __restrict__ vmask)
{
    const int b   = blockIdx.x;
    const int tid = threadIdx.x;

    __shared__ float s_vm[TT];
    __shared__ float s_bce[TT];
    __shared__ float red[NPAIR][TPB / 32];

    // ---- tiny BCE part: threads 0..15 handle the 16 timesteps of this b ----
    if (tid < TT) {
        int idx   = b * TT + tid;
        float v   = (float)vmask[idx];
        float y   = (float)tgt[idx];
        float p   = pred[idx];
        // pos_weight = 2.0
        float bce = -(2.f * y * log_sigmoid(p) + (1.f - y) * log_sigmoid(-p));
        s_vm[tid]  = v;
        s_bce[tid] = bce * v;
    }

    // ---- streaming smoothness: each thread owns 8 r columns (2 float4) ----
    const float4* base = (const float4*)rs + (size_t)b * TT * (RR / 4);
    float4 p0 = base[tid];
    float4 p1 = base[tid + TPB];

    float acc[NPAIR];
#pragma unroll
    for (int t = 0; t < NPAIR; t++) acc[t] = 0.f;

#pragma unroll
    for (int t = 1; t < TT; t++) {
        float4 c0 = base[t * (RR / 4) + tid];
        float4 c1 = base[t * (RR / 4) + tid + TPB];
        float a = 0.f;
        a += pen1(c0.x, p0.x);  a += pen1(c0.y, p0.y);
        a += pen1(c0.z, p0.z);  a += pen1(c0.w, p0.w);
        a += pen1(c1.x, p1.x);  a += pen1(c1.y, p1.y);
        a += pen1(c1.z, p1.z);  a += pen1(c1.w, p1.w);
        acc[t - 1] = a;
        p0 = c0; p1 = c1;
    }

    // ---- block reduction of the 15 per-t sums ----
    const int lane = tid & 31, wid = tid >> 5;
#pragma unroll
    for (int t = 0; t < NPAIR; t++) {
        float v = acc[t];
#pragma unroll
        for (int o = 16; o; o >>= 1) v += __shfl_xor_sync(0xffffffffu, v, o);
        if (lane == 0) red[t][wid] = v;
    }
    __syncthreads();

    // ---- global accumulation via atomics (becomes REDG; ~1us total, hidden) ----
    if (tid < NPAIR) {
        float pv = (s_vm[tid] > 0.5f && s_vm[tid + 1] > 0.5f) ? 1.f : 0.f;
        if (pv > 0.f) {
            float s = 0.f;
#pragma unroll
            for (int w = 0; w < TPB / 32; w++) s += red[tid][w];
            atomicAdd(&g_acc[tid], s);
            atomicAdd(&g_acc[NPAIR + tid], 1.f);
        }
    }
    if (tid == 0) {
        float bs = 0.f, vs = 0.f;
#pragma unroll
        for (int t = 0; t < TT; t++) { bs += s_bce[t]; vs += s_vm[t]; }
        atomicAdd(&g_acc[30], bs);
        atomicAdd(&g_acc[31], vs);
    }
}

__global__ __launch_bounds__(32)
void finalize_kernel(float* __restrict__ out)
{
    const int tid = threadIdx.x;
    __shared__ float v[32];

    v[tid] = g_acc[tid];
    __syncwarp();

    // safe to zero now: all threads computed from the shared copy
    g_acc[tid] = 0.f;

    if (tid == 0) {
        float ssum = 0.f;
        int ns = 0;
#pragma unroll
        for (int t = 0; t < NPAIR; t++) {
            float c = v[NPAIR + t];
            if (c > 0.f) ns++;
            ssum += v[t] / ((float)RR * fmaxf(c, 1.f));
        }
        float smooth = (ns > 0) ? (ssum / (float)ns) : 0.f;
        float cls    = v[30] / fmaxf(v[31], 1e-8f);
        out[0] = cls + 0.2f * smooth;
    }
}

extern "C" void kernel_launch(void* const* d_in, const int* in_sizes, int n_in,
                              void* d_out, int out_size)
{
    const float* pred  = (const float*)d_in[0];  // [B,T,1]
    const float* rs    = (const float*)d_in[1];  // [B,T,R,1]
    const int*   tgt   = (const int*)d_in[2];    // [B,T]
    const int*   vmask = (const int*)d_in[3];    // [B,T]
    float*       out   = (float*)d_out;

    smooth_kernel<<<BB, TPB>>>(pred, rs, tgt, vmask);
    finalize_kernel<<<1, 32>>>(out);
}